// round 11
// baseline (speedup 1.0000x reference)
#include <cuda_runtime.h>
#include <cuda_fp16.h>
#include <cstdint>
#include <cstddef>

// Problem constants
namespace {
constexpr int kB  = 64;
constexpr int kN  = 64;
constexpr int kC  = 8;
constexpr int kF  = 256;
constexpr int kO  = 2048;   // OC*OF
constexpr int kCF = 2048;   // C*F
constexpr int kBN = 4096;   // B*N
constexpr int kMp = 4224;   // 4096 zn + 64 zx + 64 pad
}

// Scratch (device globals; no allocation allowed)
__device__ float g_w1sum[kF];
__device__ float g_w2sum[kF];
__device__ float g_s1[kB];
__device__ float g_w[kBN];
__device__ float g_t[kB * kCF];
__device__ __half g_adjh[(size_t)kB * kC * kF * kF];   // 67 MB: [b][c][a][d] fp16 hi
__device__ __half g_A2h[(size_t)kMp * kCF];            // 17.3 MB: zn|zx fp16
__device__ __half g_B2h[(size_t)kO * kCF];             // 8.4 MB: Wc fp16

// ---------------------------------------------------------------------------
// MUFU helpers
// ---------------------------------------------------------------------------
__device__ __forceinline__ float asqrt(float x) {
    float r; asm("sqrt.approx.f32 %0, %1;" : "=f"(r) : "f"(x)); return r;
}
__device__ __forceinline__ float arcp(float x) {
    float r; asm("rcp.approx.f32 %0, %1;" : "=f"(r) : "f"(x)); return r;
}
__device__ __forceinline__ float sgnroot(float a) {
    float s = asqrt(fmaxf(fabsf(a), 1e-8f));
    return (a == 0.0f) ? 0.0f : copysignf(s, a);
}

__device__ __forceinline__ float block_reduce_256(float v) {
    __shared__ float sh[8];
    int lane = threadIdx.x & 31, w = threadIdx.x >> 5;
    #pragma unroll
    for (int o = 16; o; o >>= 1) v += __shfl_xor_sync(0xffffffffu, v, o);
    if (lane == 0) sh[w] = v;
    __syncthreads();
    v = (threadIdx.x < 8) ? sh[threadIdx.x] : 0.0f;
    if (w == 0) {
        #pragma unroll
        for (int o = 4; o; o >>= 1) v += __shfl_xor_sync(0xffffffffu, v, o);
    }
    return v;
}

__device__ __forceinline__ uint32_t s2u(const void* p) {
    uint32_t a;
    asm("{ .reg .u64 t; cvta.to.shared.u64 t, %1; cvt.u32.u64 %0, t; }" : "=r"(a) : "l"(p));
    return a;
}

// ---------------------------------------------------------------------------
// K0: column sums of W1 / W2
// ---------------------------------------------------------------------------
__global__ void k_wsum(const float* __restrict__ W1, const float* __restrict__ W2) {
    int f = threadIdx.x;
    float s1 = 0.f, s2 = 0.f;
    #pragma unroll
    for (int c = 0; c < kC; c++) {
        s1 += W1[c * kF + f];
        s2 += W2[c * kF + f];
    }
    g_w1sum[f] = s1;
    g_w2sum[f] = s2;
}

// K1: s1[b]
__global__ void k_s1(const float* __restrict__ x) {
    int b = blockIdx.x;
    float acc = 0.f;
    const float* p = x + (size_t)b * kCF;
    for (int i = threadIdx.x; i < kCF; i += 256)
        acc = fmaf(p[i], g_w1sum[i & (kF - 1)], acc);
    acc = block_reduce_256(acc);
    if (threadIdx.x == 0) g_s1[b] = acc;
}

// K2: w[b,n]
__global__ void k_w(const float* __restrict__ nb) {
    int bn = blockIdx.x;
    float acc = 0.f;
    const float* p = nb + (size_t)bn * kCF;
    for (int i = threadIdx.x; i < kCF; i += 256)
        acc = fmaf(p[i], g_w2sum[i & (kF - 1)], acc);
    acc = block_reduce_256(acc);
    if (threadIdx.x == 0) g_w[bn] = g_s1[bn >> 6] * acc;
}

// K3: t[b,c,f]
__global__ void k_t(const float* __restrict__ nb) {
    int bc = blockIdx.x;
    int b = bc >> 3, c = bc & 7;
    __shared__ float ws[kN];
    if (threadIdx.x < kN) ws[threadIdx.x] = g_w[b * kN + threadIdx.x];
    __syncthreads();
    int f = threadIdx.x;
    const float* p = nb + ((size_t)b * kN) * kCF + c * kF + f;
    float acc = 0.f;
    #pragma unroll 8
    for (int n = 0; n < kN; n++) acc = fmaf(ws[n], p[(size_t)n * kCF], acc);
    g_t[(size_t)bc * kF + f] = acc;
}

// ---------------------------------------------------------------------------
// K4: adj -> g_adjh fp16 (hi only) [b][c][a][d]  + fused zx -> g_A2h rows 4096+
// zx[b,c,a] = sum_d adj[b,c,a,d] * x[b,c,d]  (computed from pre-round fp32 adj)
// ---------------------------------------------------------------------------
__global__ void __launch_bounds__(256) k_adj(const float* __restrict__ x) {
    int b = blockIdx.y;
    int at = blockIdx.x;
    __shared__ float xs[kCF];
    __shared__ float ts[kCF];
    __shared__ float zsh[8][8];   // [warp][c]
    for (int i = threadIdx.x; i < kCF; i += 256) {
        xs[i] = x[(size_t)b * kCF + i];
        ts[i] = g_t[(size_t)b * kCF + i];
    }
    __syncthreads();
    int d = threadIdx.x;
    int lane = d & 31, w = d >> 5;
    float xd[kC], td[kC];
    #pragma unroll
    for (int c = 0; c < kC; c++) { xd[c] = xs[c * kF + d]; td[c] = ts[c * kF + d]; }

    for (int ai = 0; ai < 16; ai++) {
        int a = at * 16 + ai;
        float v[kC];
        float norm = 0.f;
        #pragma unroll
        for (int c = 0; c < kC; c++) {
            float va = xs[c * kF + a] * td[c] + xd[c] * ts[c * kF + a];
            float sv = sgnroot(va);
            v[c] = sv;
            norm += fabsf(sv);
        }
        float inv = arcp(norm + 1e-7f);
        float p[kC];
        #pragma unroll
        for (int c = 0; c < kC; c++) {
            float av = v[c] * inv;
            g_adjh[((size_t)(b * kC + c) * kF + a) * kF + d] = __float2half_rn(av);
            p[c] = av * xd[c];     // xd[c] == xs[c*kF + d]
        }
        // warp-reduce the 8 partials
        #pragma unroll
        for (int o = 16; o; o >>= 1) {
            #pragma unroll
            for (int c = 0; c < kC; c++)
                p[c] += __shfl_xor_sync(0xffffffffu, p[c], o);
        }
        if (lane == 0) {
            #pragma unroll
            for (int c = 0; c < kC; c++) zsh[w][c] = p[c];
        }
        __syncthreads();
        if (threadIdx.x < 8) {
            float z = 0.f;
            #pragma unroll
            for (int ww = 0; ww < 8; ww++) z += zsh[ww][threadIdx.x];
            g_A2h[(size_t)(4096 + b) * kCF + threadIdx.x * kF + a] = __float2half_rn(z);
        }
        __syncthreads();
    }
}

// ---------------------------------------------------------------------------
// K6: zn via HMMA: per (b,c)  C[64 n x 256 a] = NB[64 x 256 d] @ ADJ[256 a x 256 d]^T
// single-term fp16: nh . ah
// smem: NB 4 chunks x 8KB = 32 KB, ADJ 2 x 32 KB stages.
// ---------------------------------------------------------------------------
namespace {
constexpr uint32_t kNbRegion = 32768;
constexpr uint32_t kAdjStage = 32768;
constexpr uint32_t kSmemZn   = kNbRegion + 2 * kAdjStage;  // 96 KB
}

__global__ void __launch_bounds__(256) k_zn_mma(const float* __restrict__ nb) {
    extern __shared__ char sm[];
    int tid = threadIdx.x, lane = tid & 31, wid = tid >> 5;
    int wm = wid >> 2, wn = wid & 3;             // 2(m) x 4(n); warp tile 32x64
    int bc = blockIdx.x;
    int b = bc >> 3, c = bc & 7;
    uint32_t sb = s2u(sm);
    uint32_t nbB = sb, adjB = sb + kNbRegion;

    const char* adj_bc = (const char*)(g_adjh + (size_t)bc * kF * kF);  // row 512 B
    const float* nb_bc = nb + ((size_t)b * kN) * kCF + c * kF;

    // load adj d-chunk q (64 d = 128 B per a-row) into stage q&1
    auto stage_load = [&](int q) {
        int srcoff = q * 128;
        uint32_t base = adjB + (uint32_t)(q & 1) * kAdjStage;
        #pragma unroll
        for (int k = 0; k < 8; k++) {
            int u = tid + (k << 8);          // 2048 quads: 256 rows x 8
            int row = u >> 3, q8 = u & 7;
            const char* g = adj_bc + (size_t)row * 512 + srcoff + q8 * 16;
            uint32_t so = base + (uint32_t)(row * 128) + (uint32_t)((q8 * 16) ^ ((row & 7) << 4));
            asm volatile("cp.async.cg.shared.global [%0], [%1], 16;" :: "r"(so), "l"(g));
        }
        asm volatile("cp.async.commit_group;");
    };

    stage_load(0);

    // NB load + fp16 convert into smem chunks (overlaps first adj load)
    #pragma unroll
    for (int itc = 0; itc < 8; itc++) {
        int e = tid + (itc << 8);            // 2048 groups: 64 rows x 32 (8 d each)
        int row = e >> 5, d0 = (e & 31) << 3;
        float4 v0 = *(const float4*)(nb_bc + (size_t)row * kCF + d0);
        float4 v1 = *(const float4*)(nb_bc + (size_t)row * kCF + d0 + 4);
        float v[8] = {v0.x, v0.y, v0.z, v0.w, v1.x, v1.y, v1.z, v1.w};
        uint32_t hw[4];
        #pragma unroll
        for (int j = 0; j < 4; j++) {
            __half h0 = __float2half_rn(v[2 * j]), h1 = __float2half_rn(v[2 * j + 1]);
            hw[j] = (uint32_t)__half_as_ushort(h0) | ((uint32_t)__half_as_ushort(h1) << 16);
        }
        int chunk = d0 >> 6, cw = d0 & 63;
        uint32_t off = (uint32_t)(chunk * 8192 + row * 128) + (uint32_t)((cw * 2) ^ ((row & 7) << 4));
        *(uint4*)(sm + off) = make_uint4(hw[0], hw[1], hw[2], hw[3]);
    }

    float acc[2][8][4];
    #pragma unroll
    for (int i = 0; i < 2; i++)
        #pragma unroll
        for (int j = 0; j < 8; j++)
            #pragma unroll
            for (int r = 0; r < 4; r++) acc[i][j][r] = 0.f;

    int aRow0 = wm * 32 + (lane & 15);
    int aKofs = (lane >> 4) << 4;
    int bRow0 = wn * 64 + (lane & 7) + ((lane & 16) >> 1);
    int bKofs = (lane & 8) << 1;

    const int NIT = 4;   // 4 d-chunks of 64
    for (int it = 0; it < NIT; it++) {
        if (it + 1 < NIT) {
            stage_load(it + 1);
            asm volatile("cp.async.wait_group 1;");
        } else {
            asm volatile("cp.async.wait_group 0;");
        }
        __syncthreads();
        uint32_t aH = nbB + (uint32_t)it * 8192u;           // nh chunk
        uint32_t bBase = adjB + (uint32_t)(it & 1) * kAdjStage;
        #pragma unroll
        for (int k16 = 0; k16 < 4; k16++) {
            int kb = k16 * 32;
            uint32_t af[2][4];
            #pragma unroll
            for (int mt = 0; mt < 2; mt++) {
                int row = aRow0 + mt * 16;
                uint32_t sw = ((kb + aKofs) ^ ((row & 7) << 4)) + row * 128;
                asm volatile("ldmatrix.sync.aligned.m8n8.x4.shared.b16 {%0,%1,%2,%3}, [%4];"
                             : "=r"(af[mt][0]), "=r"(af[mt][1]), "=r"(af[mt][2]), "=r"(af[mt][3])
                             : "r"(aH + sw));
            }
            uint32_t bf[4][4];
            #pragma unroll
            for (int nt = 0; nt < 4; nt++) {
                int row = bRow0 + nt * 16;
                uint32_t bd = bBase + row * 128 + ((kb + bKofs) ^ ((row & 7) << 4));
                asm volatile("ldmatrix.sync.aligned.m8n8.x4.shared.b16 {%0,%1,%2,%3}, [%4];"
                             : "=r"(bf[nt][0]), "=r"(bf[nt][1]), "=r"(bf[nt][2]), "=r"(bf[nt][3])
                             : "r"(bd));
            }
            #pragma unroll
            for (int mt = 0; mt < 2; mt++)
                #pragma unroll
                for (int n8 = 0; n8 < 8; n8++) {
                    uint32_t b0 = bf[n8 >> 1][(n8 & 1) * 2 + 0];
                    uint32_t b1 = bf[n8 >> 1][(n8 & 1) * 2 + 1];
                    asm volatile(
                        "mma.sync.aligned.m16n8k16.row.col.f32.f16.f16.f32 "
                        "{%0,%1,%2,%3}, {%4,%5,%6,%7}, {%8,%9}, {%0,%1,%2,%3};"
                        : "+f"(acc[mt][n8][0]), "+f"(acc[mt][n8][1]),
                          "+f"(acc[mt][n8][2]), "+f"(acc[mt][n8][3])
                        : "r"(af[mt][0]), "r"(af[mt][1]), "r"(af[mt][2]), "r"(af[mt][3]),
                          "r"(b0), "r"(b1));
                }
        }
        __syncthreads();
    }

    // epilogue: fp16 store into g_A2h rows b*64 + n, cols c*256 + a
    int g = lane >> 2, tig = lane & 3;
    #pragma unroll
    for (int mt = 0; mt < 2; mt++) {
        #pragma unroll
        for (int half = 0; half < 2; half++) {
            int lr = wm * 32 + mt * 16 + g + half * 8;
            __half* dst = g_A2h + (size_t)(b * kN + lr) * kCF + c * kF;
            #pragma unroll
            for (int n8 = 0; n8 < 8; n8++) {
                int col = wn * 64 + n8 * 8 + tig * 2;
                *(__half2*)(dst + col) =
                    __halves2half2(__float2half_rn(acc[mt][n8][half * 2]),
                                   __float2half_rn(acc[mt][n8][half * 2 + 1]));
            }
        }
    }
}

// ---------------------------------------------------------------------------
// K7: Wc -> g_B2h fp16 (vectorized)
// ---------------------------------------------------------------------------
__global__ void k_wconv(const float* __restrict__ Wc) {
    int o = blockIdx.x;
    __half* rowb = g_B2h + (size_t)o * kCF;
    const float* src = Wc + (size_t)o * kCF;
    #pragma unroll
    for (int it = 0; it < 2; it++) {
        int j = (threadIdx.x + it * 256) * 4;
        float4 v = *(const float4*)(src + j);
        __half2 h0 = __halves2half2(__float2half_rn(v.x), __float2half_rn(v.y));
        __half2 h1 = __halves2half2(__float2half_rn(v.z), __float2half_rn(v.w));
        *(__half2*)(rowb + j)     = h0;
        *(__half2*)(rowb + j + 2) = h1;
    }
}

// ---------------------------------------------------------------------------
// K8: single-term fp16 NT GEMM: C[4224,2048] = A2h @ B2h^T, K=2048
// CTA 128x128, 8 warps 4x2, double-buffered cp.async, NIT=32, 2 CTA/SM.
// ---------------------------------------------------------------------------
namespace {
constexpr uint32_t kStage = 32768;   // A 16K + B 16K
constexpr uint32_t kSmemG = 2 * kStage;
}

__global__ void __launch_bounds__(256, 2) k_mma2(float* __restrict__ x_out,
                                                 float* __restrict__ n_out) {
    extern __shared__ char sm[];
    int tid = threadIdx.x, lane = tid & 31, wid = tid >> 5;
    int wm = wid >> 1, wn = wid & 1;             // 4(m) x 2(n)
    int bm = blockIdx.y * 128, bn = blockIdx.x * 128;
    uint32_t sbase = s2u(sm);

    const char* Ag = (const char*)(g_A2h + (size_t)bm * kCF);   // row 4096 B
    const char* Bg = (const char*)(g_B2h + (size_t)bn * kCF);   // row 4096 B

    auto stage_load = [&](int it) {
        int koff = it * 128;                     // 64 halves
        uint32_t base = sbase + (uint32_t)(it & 1) * kStage;
        #pragma unroll
        for (int k = 0; k < 8; k++) {
            int u = tid + (k << 8);
            int isB = u >> 10;
            int v = u & 1023;
            int row = v >> 3, q8 = v & 7;
            const char* g = (isB ? Bg : Ag) + (size_t)row * 4096 + koff + q8 * 16;
            uint32_t so = base + (uint32_t)isB * 16384u + (uint32_t)(row * 128)
                          + (uint32_t)((q8 * 16) ^ ((row & 7) << 4));
            asm volatile("cp.async.cg.shared.global [%0], [%1], 16;" :: "r"(so), "l"(g));
        }
        asm volatile("cp.async.commit_group;");
    };

    float acc[2][8][4];
    #pragma unroll
    for (int i = 0; i < 2; i++)
        #pragma unroll
        for (int j = 0; j < 8; j++)
            #pragma unroll
            for (int r = 0; r < 4; r++) acc[i][j][r] = 0.f;

    int aRow0 = wm * 32 + (lane & 15);
    int aKofs = (lane >> 4) << 4;
    int bRow0 = wn * 64 + (lane & 7) + ((lane & 16) >> 1);
    int bKofs = (lane & 8) << 1;

    stage_load(0);
    const int NIT = 32;
    for (int it = 0; it < NIT; it++) {
        int s = it & 1;
        if (it + 1 < NIT) {
            stage_load(it + 1);
            asm volatile("cp.async.wait_group 1;");
        } else {
            asm volatile("cp.async.wait_group 0;");
        }
        __syncthreads();
        uint32_t aA = sbase + (uint32_t)s * kStage;
        uint32_t aB = aA + 16384u;
        #pragma unroll
        for (int k16 = 0; k16 < 4; k16++) {
            int kb = k16 * 32;
            uint32_t af[2][4];
            #pragma unroll
            for (int mt = 0; mt < 2; mt++) {
                int row = aRow0 + mt * 16;
                uint32_t ad = aA + row * 128 + ((kb + aKofs) ^ ((row & 7) << 4));
                asm volatile("ldmatrix.sync.aligned.m8n8.x4.shared.b16 {%0,%1,%2,%3}, [%4];"
                             : "=r"(af[mt][0]), "=r"(af[mt][1]), "=r"(af[mt][2]), "=r"(af[mt][3])
                             : "r"(ad));
            }
            uint32_t bf[4][4];
            #pragma unroll
            for (int nt = 0; nt < 4; nt++) {
                int row = bRow0 + nt * 16;
                uint32_t bd = aB + row * 128 + ((kb + bKofs) ^ ((row & 7) << 4));
                asm volatile("ldmatrix.sync.aligned.m8n8.x4.shared.b16 {%0,%1,%2,%3}, [%4];"
                             : "=r"(bf[nt][0]), "=r"(bf[nt][1]), "=r"(bf[nt][2]), "=r"(bf[nt][3])
                             : "r"(bd));
            }
            #pragma unroll
            for (int mt = 0; mt < 2; mt++)
                #pragma unroll
                for (int n8 = 0; n8 < 8; n8++) {
                    uint32_t b0 = bf[n8 >> 1][(n8 & 1) * 2 + 0];
                    uint32_t b1 = bf[n8 >> 1][(n8 & 1) * 2 + 1];
                    asm volatile(
                        "mma.sync.aligned.m16n8k16.row.col.f32.f16.f16.f32 "
                        "{%0,%1,%2,%3}, {%4,%5,%6,%7}, {%8,%9}, {%0,%1,%2,%3};"
                        : "+f"(acc[mt][n8][0]), "+f"(acc[mt][n8][1]),
                          "+f"(acc[mt][n8][2]), "+f"(acc[mt][n8][3])
                        : "r"(af[mt][0]), "r"(af[mt][1]), "r"(af[mt][2]), "r"(af[mt][3]),
                          "r"(b0), "r"(b1));
                }
        }
        __syncthreads();
    }

    int g = lane >> 2, tig = lane & 3;
    #pragma unroll
    for (int mt = 0; mt < 2; mt++) {
        #pragma unroll
        for (int half = 0; half < 2; half++) {
            int gm = bm + wm * 32 + mt * 16 + g + half * 8;
            if (gm < 4160) {
                float* dst = (gm < 4096)
                    ? n_out + (size_t)gm * kO
                    : x_out + (size_t)(gm - 4096) * kO;
                #pragma unroll
                for (int n8 = 0; n8 < 8; n8++) {
                    int col = bn + wn * 64 + n8 * 8 + tig * 2;
                    float2 v = half ? make_float2(acc[mt][n8][2], acc[mt][n8][3])
                                    : make_float2(acc[mt][n8][0], acc[mt][n8][1]);
                    *(float2*)(dst + col) = v;
                }
            }
        }
    }
}

// ---------------------------------------------------------------------------
extern "C" void kernel_launch(void* const* d_in, const int* in_sizes, int n_in,
                              void* d_out, int out_size) {
    const float* x  = (const float*)d_in[0];
    const float* nb = (const float*)d_in[1];
    const float* W1 = (const float*)d_in[2];
    const float* W2 = (const float*)d_in[3];
    const float* Wc = (const float*)d_in[4];
    float* out = (float*)d_out;
    float* x_out = out;                          // (B, OC, OF)
    float* n_out = out + (size_t)kB * kO;        // (B, N, OC, OF)

    cudaFuncSetAttribute(k_zn_mma, cudaFuncAttributeMaxDynamicSharedMemorySize, kSmemZn);
    cudaFuncSetAttribute(k_mma2, cudaFuncAttributeMaxDynamicSharedMemorySize, kSmemG);

    k_wsum<<<1, 256>>>(W1, W2);
    k_s1<<<kB, 256>>>(x);
    k_w<<<kBN, 256>>>(nb);
    k_t<<<kB * kC, 256>>>(nb);
    k_adj<<<dim3(16, kB), 256>>>(x);
    k_zn_mma<<<kB * kC, 256, kSmemZn>>>(nb);
    k_wconv<<<kO, 256>>>(Wc);
    k_mma2<<<dim3(16, 33), 256, kSmemG>>>(x_out, n_out);
}

// round 13
// speedup vs baseline: 1.0337x; 1.0337x over previous
#include <cuda_runtime.h>
#include <cuda_fp16.h>
#include <cstdint>
#include <cstddef>

// Problem constants
namespace {
constexpr int kB  = 64;
constexpr int kN  = 64;
constexpr int kC  = 8;
constexpr int kF  = 256;
constexpr int kO  = 2048;   // OC*OF
constexpr int kCF = 2048;   // C*F
constexpr int kBN = 4096;   // B*N
constexpr int kMp = 4224;   // 4096 zn + 64 zx + 64 pad
}

// Scratch (device globals; no allocation allowed)
__device__ float g_w1sum[kF];
__device__ float g_w2sum[kF];
__device__ float g_s1[kB];
__device__ float g_w[kBN];
__device__ float g_t[kB * kCF];
__device__ __half g_adjh[(size_t)kB * kC * kF * kF];   // 67 MB: [b][c][a][d] fp16 hi
__device__ __half g_A2h[(size_t)kMp * kCF];            // 17.3 MB: zn|zx fp16
__device__ __half g_B2h[(size_t)kO * kCF];             // 8.4 MB: Wc fp16

// ---------------------------------------------------------------------------
// MUFU helpers
// ---------------------------------------------------------------------------
__device__ __forceinline__ float asqrt(float x) {
    float r; asm("sqrt.approx.f32 %0, %1;" : "=f"(r) : "f"(x)); return r;
}
__device__ __forceinline__ float arcp(float x) {
    float r; asm("rcp.approx.f32 %0, %1;" : "=f"(r) : "f"(x)); return r;
}
__device__ __forceinline__ float sgnroot(float a) {
    float s = asqrt(fmaxf(fabsf(a), 1e-8f));
    return (a == 0.0f) ? 0.0f : copysignf(s, a);
}

__device__ __forceinline__ float block_reduce_256(float v) {
    __shared__ float sh[8];
    int lane = threadIdx.x & 31, w = threadIdx.x >> 5;
    #pragma unroll
    for (int o = 16; o; o >>= 1) v += __shfl_xor_sync(0xffffffffu, v, o);
    if (lane == 0) sh[w] = v;
    __syncthreads();
    v = (threadIdx.x < 8) ? sh[threadIdx.x] : 0.0f;
    if (w == 0) {
        #pragma unroll
        for (int o = 4; o; o >>= 1) v += __shfl_xor_sync(0xffffffffu, v, o);
    }
    return v;
}

__device__ __forceinline__ uint32_t s2u(const void* p) {
    uint32_t a;
    asm("{ .reg .u64 t; cvta.to.shared.u64 t, %1; cvt.u32.u64 %0, t; }" : "=r"(a) : "l"(p));
    return a;
}

// ---------------------------------------------------------------------------
// K0: column sums of W1 / W2
// ---------------------------------------------------------------------------
__global__ void k_wsum(const float* __restrict__ W1, const float* __restrict__ W2) {
    int f = threadIdx.x;
    float s1 = 0.f, s2 = 0.f;
    #pragma unroll
    for (int c = 0; c < kC; c++) {
        s1 += W1[c * kF + f];
        s2 += W2[c * kF + f];
    }
    g_w1sum[f] = s1;
    g_w2sum[f] = s2;
}

// K1: s1[b]
__global__ void k_s1(const float* __restrict__ x) {
    int b = blockIdx.x;
    float acc = 0.f;
    const float* p = x + (size_t)b * kCF;
    for (int i = threadIdx.x; i < kCF; i += 256)
        acc = fmaf(p[i], g_w1sum[i & (kF - 1)], acc);
    acc = block_reduce_256(acc);
    if (threadIdx.x == 0) g_s1[b] = acc;
}

// K2: w[b,n]
__global__ void k_w(const float* __restrict__ nb) {
    int bn = blockIdx.x;
    float acc = 0.f;
    const float* p = nb + (size_t)bn * kCF;
    for (int i = threadIdx.x; i < kCF; i += 256)
        acc = fmaf(p[i], g_w2sum[i & (kF - 1)], acc);
    acc = block_reduce_256(acc);
    if (threadIdx.x == 0) g_w[bn] = g_s1[bn >> 6] * acc;
}

// K3: t[b,c,f]
__global__ void k_t(const float* __restrict__ nb) {
    int bc = blockIdx.x;
    int b = bc >> 3, c = bc & 7;
    __shared__ float ws[kN];
    if (threadIdx.x < kN) ws[threadIdx.x] = g_w[b * kN + threadIdx.x];
    __syncthreads();
    int f = threadIdx.x;
    const float* p = nb + ((size_t)b * kN) * kCF + c * kF + f;
    float acc = 0.f;
    #pragma unroll 8
    for (int n = 0; n < kN; n++) acc = fmaf(ws[n], p[(size_t)n * kCF], acc);
    g_t[(size_t)bc * kF + f] = acc;
}

// ---------------------------------------------------------------------------
// K4: adj -> g_adjh fp16 (hi only) [b][c][a][d]  + fused zx (single sync/tile)
// zx[b,c,a] = sum_d adj[b,c,a,d] * x[b,c,d]  (pre-round fp32 adj)
// ---------------------------------------------------------------------------
__global__ void __launch_bounds__(256) k_adj(const float* __restrict__ x) {
    int b = blockIdx.y;
    int at = blockIdx.x;
    __shared__ float xs[kCF];
    __shared__ float ts[kCF];
    __shared__ float zsh[16][8][8];   // [ai][warp][c], no sync inside ai loop
    for (int i = threadIdx.x; i < kCF; i += 256) {
        xs[i] = x[(size_t)b * kCF + i];
        ts[i] = g_t[(size_t)b * kCF + i];
    }
    __syncthreads();
    int d = threadIdx.x;
    int lane = d & 31, w = d >> 5;
    float xd[kC], td[kC];
    #pragma unroll
    for (int c = 0; c < kC; c++) { xd[c] = xs[c * kF + d]; td[c] = ts[c * kF + d]; }

    for (int ai = 0; ai < 16; ai++) {
        int a = at * 16 + ai;
        float v[kC];
        float norm = 0.f;
        #pragma unroll
        for (int c = 0; c < kC; c++) {
            float va = xs[c * kF + a] * td[c] + xd[c] * ts[c * kF + a];
            float sv = sgnroot(va);
            v[c] = sv;
            norm += fabsf(sv);
        }
        float inv = arcp(norm + 1e-7f);
        float p[kC];
        #pragma unroll
        for (int c = 0; c < kC; c++) {
            float av = v[c] * inv;
            g_adjh[((size_t)(b * kC + c) * kF + a) * kF + d] = __float2half_rn(av);
            p[c] = av * xd[c];
        }
        #pragma unroll
        for (int o = 16; o; o >>= 1) {
            #pragma unroll
            for (int c = 0; c < kC; c++)
                p[c] += __shfl_xor_sync(0xffffffffu, p[c], o);
        }
        if (lane == 0) {
            #pragma unroll
            for (int c = 0; c < kC; c++) zsh[ai][w][c] = p[c];
        }
    }
    __syncthreads();
    if (threadIdx.x < 128) {
        int ai = threadIdx.x >> 3, c = threadIdx.x & 7;
        float z = 0.f;
        #pragma unroll
        for (int ww = 0; ww < 8; ww++) z += zsh[ai][ww][c];
        g_A2h[(size_t)(4096 + b) * kCF + c * kF + at * 16 + ai] = __float2half_rn(z);
    }
}

// ---------------------------------------------------------------------------
// K6: zn via HMMA: per (b,c)  C[64 n x 256 a] = NB[64 x 256 d] @ ADJ[256 a x 256 d]^T
// single-term fp16: nh . ah
// smem: NB 4 chunks x 8KB = 32 KB, ADJ 2 x 32 KB stages.
// ---------------------------------------------------------------------------
namespace {
constexpr uint32_t kNbRegion = 32768;
constexpr uint32_t kAdjStage = 32768;
constexpr uint32_t kSmemZn   = kNbRegion + 2 * kAdjStage;  // 96 KB
}

__global__ void __launch_bounds__(256) k_zn_mma(const float* __restrict__ nb) {
    extern __shared__ char sm[];
    int tid = threadIdx.x, lane = tid & 31, wid = tid >> 5;
    int wm = wid >> 2, wn = wid & 3;             // 2(m) x 4(n); warp tile 32x64
    int bc = blockIdx.x;
    int b = bc >> 3, c = bc & 7;
    uint32_t sb = s2u(sm);
    uint32_t nbB = sb, adjB = sb + kNbRegion;

    const char* adj_bc = (const char*)(g_adjh + (size_t)bc * kF * kF);  // row 512 B
    const float* nb_bc = nb + ((size_t)b * kN) * kCF + c * kF;

    auto stage_load = [&](int q) {
        int srcoff = q * 128;
        uint32_t base = adjB + (uint32_t)(q & 1) * kAdjStage;
        #pragma unroll
        for (int k = 0; k < 8; k++) {
            int u = tid + (k << 8);          // 2048 quads: 256 rows x 8
            int row = u >> 3, q8 = u & 7;
            const char* g = adj_bc + (size_t)row * 512 + srcoff + q8 * 16;
            uint32_t so = base + (uint32_t)(row * 128) + (uint32_t)((q8 * 16) ^ ((row & 7) << 4));
            asm volatile("cp.async.cg.shared.global [%0], [%1], 16;" :: "r"(so), "l"(g));
        }
        asm volatile("cp.async.commit_group;");
    };

    stage_load(0);

    // NB load + fp16 convert into smem chunks (overlaps first adj load)
    #pragma unroll
    for (int itc = 0; itc < 8; itc++) {
        int e = tid + (itc << 8);            // 2048 groups: 64 rows x 32 (8 d each)
        int row = e >> 5, d0 = (e & 31) << 3;
        float4 v0 = *(const float4*)(nb_bc + (size_t)row * kCF + d0);
        float4 v1 = *(const float4*)(nb_bc + (size_t)row * kCF + d0 + 4);
        float v[8] = {v0.x, v0.y, v0.z, v0.w, v1.x, v1.y, v1.z, v1.w};
        uint32_t hw[4];
        #pragma unroll
        for (int j = 0; j < 4; j++) {
            __half h0 = __float2half_rn(v[2 * j]), h1 = __float2half_rn(v[2 * j + 1]);
            hw[j] = (uint32_t)__half_as_ushort(h0) | ((uint32_t)__half_as_ushort(h1) << 16);
        }
        int chunk = d0 >> 6, cw = d0 & 63;
        uint32_t off = (uint32_t)(chunk * 8192 + row * 128) + (uint32_t)((cw * 2) ^ ((row & 7) << 4));
        *(uint4*)(sm + off) = make_uint4(hw[0], hw[1], hw[2], hw[3]);
    }

    float acc[2][8][4];
    #pragma unroll
    for (int i = 0; i < 2; i++)
        #pragma unroll
        for (int j = 0; j < 8; j++)
            #pragma unroll
            for (int r = 0; r < 4; r++) acc[i][j][r] = 0.f;

    int aRow0 = wm * 32 + (lane & 15);
    int aKofs = (lane >> 4) << 4;
    int bRow0 = wn * 64 + (lane & 7) + ((lane & 16) >> 1);
    int bKofs = (lane & 8) << 1;

    const int NIT = 4;   // 4 d-chunks of 64
    for (int it = 0; it < NIT; it++) {
        if (it + 1 < NIT) {
            stage_load(it + 1);
            asm volatile("cp.async.wait_group 1;");
        } else {
            asm volatile("cp.async.wait_group 0;");
        }
        __syncthreads();
        uint32_t aH = nbB + (uint32_t)it * 8192u;
        uint32_t bBase = adjB + (uint32_t)(it & 1) * kAdjStage;
        #pragma unroll
        for (int k16 = 0; k16 < 4; k16++) {
            int kb = k16 * 32;
            uint32_t af[2][4];
            #pragma unroll
            for (int mt = 0; mt < 2; mt++) {
                int row = aRow0 + mt * 16;
                uint32_t sw = ((kb + aKofs) ^ ((row & 7) << 4)) + row * 128;
                asm volatile("ldmatrix.sync.aligned.m8n8.x4.shared.b16 {%0,%1,%2,%3}, [%4];"
                             : "=r"(af[mt][0]), "=r"(af[mt][1]), "=r"(af[mt][2]), "=r"(af[mt][3])
                             : "r"(aH + sw));
            }
            uint32_t bf[4][4];
            #pragma unroll
            for (int nt = 0; nt < 4; nt++) {
                int row = bRow0 + nt * 16;
                uint32_t bd = bBase + row * 128 + ((kb + bKofs) ^ ((row & 7) << 4));
                asm volatile("ldmatrix.sync.aligned.m8n8.x4.shared.b16 {%0,%1,%2,%3}, [%4];"
                             : "=r"(bf[nt][0]), "=r"(bf[nt][1]), "=r"(bf[nt][2]), "=r"(bf[nt][3])
                             : "r"(bd));
            }
            #pragma unroll
            for (int mt = 0; mt < 2; mt++)
                #pragma unroll
                for (int n8 = 0; n8 < 8; n8++) {
                    uint32_t b0 = bf[n8 >> 1][(n8 & 1) * 2 + 0];
                    uint32_t b1 = bf[n8 >> 1][(n8 & 1) * 2 + 1];
                    asm volatile(
                        "mma.sync.aligned.m16n8k16.row.col.f32.f16.f16.f32 "
                        "{%0,%1,%2,%3}, {%4,%5,%6,%7}, {%8,%9}, {%0,%1,%2,%3};"
                        : "+f"(acc[mt][n8][0]), "+f"(acc[mt][n8][1]),
                          "+f"(acc[mt][n8][2]), "+f"(acc[mt][n8][3])
                        : "r"(af[mt][0]), "r"(af[mt][1]), "r"(af[mt][2]), "r"(af[mt][3]),
                          "r"(b0), "r"(b1));
                }
        }
        __syncthreads();
    }

    // epilogue: fp16 store into g_A2h rows b*64 + n, cols c*256 + a
    int g = lane >> 2, tig = lane & 3;
    #pragma unroll
    for (int mt = 0; mt < 2; mt++) {
        #pragma unroll
        for (int half = 0; half < 2; half++) {
            int lr = wm * 32 + mt * 16 + g + half * 8;
            __half* dst = g_A2h + (size_t)(b * kN + lr) * kCF + c * kF;
            #pragma unroll
            for (int n8 = 0; n8 < 8; n8++) {
                int col = wn * 64 + n8 * 8 + tig * 2;
                *(__half2*)(dst + col) =
                    __halves2half2(__float2half_rn(acc[mt][n8][half * 2]),
                                   __float2half_rn(acc[mt][n8][half * 2 + 1]));
            }
        }
    }
}

// ---------------------------------------------------------------------------
// K7: Wc -> g_B2h fp16 (vectorized)
// ---------------------------------------------------------------------------
__global__ void k_wconv(const float* __restrict__ Wc) {
    int o = blockIdx.x;
    __half* rowb = g_B2h + (size_t)o * kCF;
    const float* src = Wc + (size_t)o * kCF;
    #pragma unroll
    for (int it = 0; it < 2; it++) {
        int j = (threadIdx.x + it * 256) * 4;
        float4 v = *(const float4*)(src + j);
        __half2 h0 = __halves2half2(__float2half_rn(v.x), __float2half_rn(v.y));
        __half2 h1 = __halves2half2(__float2half_rn(v.z), __float2half_rn(v.w));
        *(__half2*)(rowb + j)     = h0;
        *(__half2*)(rowb + j + 2) = h1;
    }
}

// ---------------------------------------------------------------------------
// K8: single-term fp16 NT GEMM: C[4224,2048] = A2h @ B2h^T, K=2048
// CTA 128x128, 8 warps 4x2, double-buffered cp.async, NIT=32.
// ---------------------------------------------------------------------------
namespace {
constexpr uint32_t kStage = 32768;   // A 16K + B 16K
constexpr uint32_t kSmemG = 2 * kStage;
}

__global__ void __launch_bounds__(256) k_mma2(float* __restrict__ x_out,
                                              float* __restrict__ n_out) {
    extern __shared__ char sm[];
    int tid = threadIdx.x, lane = tid & 31, wid = tid >> 5;
    int wm = wid >> 1, wn = wid & 1;             // 4(m) x 2(n)
    int bm = blockIdx.y * 128, bn = blockIdx.x * 128;
    uint32_t sbase = s2u(sm);

    const char* Ag = (const char*)(g_A2h + (size_t)bm * kCF);   // row 4096 B
    const char* Bg = (const char*)(g_B2h + (size_t)bn * kCF);   // row 4096 B

    auto stage_load = [&](int it) {
        int koff = it * 128;                     // 64 halves
        uint32_t base = sbase + (uint32_t)(it & 1) * kStage;
        #pragma unroll
        for (int k = 0; k < 8; k++) {
            int u = tid + (k << 8);
            int isB = u >> 10;
            int v = u & 1023;
            int row = v >> 3, q8 = v & 7;
            const char* g = (isB ? Bg : Ag) + (size_t)row * 4096 + koff + q8 * 16;
            uint32_t so = base + (uint32_t)isB * 16384u + (uint32_t)(row * 128)
                          + (uint32_t)((q8 * 16) ^ ((row & 7) << 4));
            asm volatile("cp.async.cg.shared.global [%0], [%1], 16;" :: "r"(so), "l"(g));
        }
        asm volatile("cp.async.commit_group;");
    };

    float acc[2][8][4];
    #pragma unroll
    for (int i = 0; i < 2; i++)
        #pragma unroll
        for (int j = 0; j < 8; j++)
            #pragma unroll
            for (int r = 0; r < 4; r++) acc[i][j][r] = 0.f;

    int aRow0 = wm * 32 + (lane & 15);
    int aKofs = (lane >> 4) << 4;
    int bRow0 = wn * 64 + (lane & 7) + ((lane & 16) >> 1);
    int bKofs = (lane & 8) << 1;

    stage_load(0);
    const int NIT = 32;
    for (int it = 0; it < NIT; it++) {
        int s = it & 1;
        if (it + 1 < NIT) {
            stage_load(it + 1);
            asm volatile("cp.async.wait_group 1;");
        } else {
            asm volatile("cp.async.wait_group 0;");
        }
        __syncthreads();
        uint32_t aA = sbase + (uint32_t)s * kStage;
        uint32_t aB = aA + 16384u;
        #pragma unroll
        for (int k16 = 0; k16 < 4; k16++) {
            int kb = k16 * 32;
            uint32_t af[2][4];
            #pragma unroll
            for (int mt = 0; mt < 2; mt++) {
                int row = aRow0 + mt * 16;
                uint32_t ad = aA + row * 128 + ((kb + aKofs) ^ ((row & 7) << 4));
                asm volatile("ldmatrix.sync.aligned.m8n8.x4.shared.b16 {%0,%1,%2,%3}, [%4];"
                             : "=r"(af[mt][0]), "=r"(af[mt][1]), "=r"(af[mt][2]), "=r"(af[mt][3])
                             : "r"(ad));
            }
            uint32_t bf[4][4];
            #pragma unroll
            for (int nt = 0; nt < 4; nt++) {
                int row = bRow0 + nt * 16;
                uint32_t bd = aB + row * 128 + ((kb + bKofs) ^ ((row & 7) << 4));
                asm volatile("ldmatrix.sync.aligned.m8n8.x4.shared.b16 {%0,%1,%2,%3}, [%4];"
                             : "=r"(bf[nt][0]), "=r"(bf[nt][1]), "=r"(bf[nt][2]), "=r"(bf[nt][3])
                             : "r"(bd));
            }
            #pragma unroll
            for (int mt = 0; mt < 2; mt++)
                #pragma unroll
                for (int n8 = 0; n8 < 8; n8++) {
                    uint32_t b0 = bf[n8 >> 1][(n8 & 1) * 2 + 0];
                    uint32_t b1 = bf[n8 >> 1][(n8 & 1) * 2 + 1];
                    asm volatile(
                        "mma.sync.aligned.m16n8k16.row.col.f32.f16.f16.f32 "
                        "{%0,%1,%2,%3}, {%4,%5,%6,%7}, {%8,%9}, {%0,%1,%2,%3};"
                        : "+f"(acc[mt][n8][0]), "+f"(acc[mt][n8][1]),
                          "+f"(acc[mt][n8][2]), "+f"(acc[mt][n8][3])
                        : "r"(af[mt][0]), "r"(af[mt][1]), "r"(af[mt][2]), "r"(af[mt][3]),
                          "r"(b0), "r"(b1));
                }
        }
        __syncthreads();
    }

    int g = lane >> 2, tig = lane & 3;
    #pragma unroll
    for (int mt = 0; mt < 2; mt++) {
        #pragma unroll
        for (int half = 0; half < 2; half++) {
            int gm = bm + wm * 32 + mt * 16 + g + half * 8;
            if (gm < 4160) {
                float* dst = (gm < 4096)
                    ? n_out + (size_t)gm * kO
                    : x_out + (size_t)(gm - 4096) * kO;
                #pragma unroll
                for (int n8 = 0; n8 < 8; n8++) {
                    int col = bn + wn * 64 + n8 * 8 + tig * 2;
                    float2 v = half ? make_float2(acc[mt][n8][2], acc[mt][n8][3])
                                    : make_float2(acc[mt][n8][0], acc[mt][n8][1]);
                    *(float2*)(dst + col) = v;
                }
            }
        }
    }
}

// ---------------------------------------------------------------------------
extern "C" void kernel_launch(void* const* d_in, const int* in_sizes, int n_in,
                              void* d_out, int out_size) {
    const float* x  = (const float*)d_in[0];
    const float* nb = (const float*)d_in[1];
    const float* W1 = (const float*)d_in[2];
    const float* W2 = (const float*)d_in[3];
    const float* Wc = (const float*)d_in[4];
    float* out = (float*)d_out;
    float* x_out = out;                          // (B, OC, OF)
    float* n_out = out + (size_t)kB * kO;        // (B, N, OC, OF)

    cudaFuncSetAttribute(k_zn_mma, cudaFuncAttributeMaxDynamicSharedMemorySize, kSmemZn);
    cudaFuncSetAttribute(k_mma2, cudaFuncAttributeMaxDynamicSharedMemorySize, kSmemG);

    k_wsum<<<1, 256>>>(W1, W2);
    k_s1<<<kB, 256>>>(x);
    k_w<<<kBN, 256>>>(nb);
    k_t<<<kB * kC, 256>>>(nb);
    k_adj<<<dim3(16, kB), 256>>>(x);
    k_zn_mma<<<kB * kC, 256, kSmemZn>>>(nb);
    k_wconv<<<kO, 256>>>(Wc);
    k_mma2<<<dim3(16, 33), 256, kSmemG>>>(x_out, n_out);
}

// round 14
// speedup vs baseline: 1.0559x; 1.0215x over previous
#include <cuda_runtime.h>
#include <cuda_fp16.h>
#include <cstdint>
#include <cstddef>

// Problem constants
namespace {
constexpr int kB  = 64;
constexpr int kN  = 64;
constexpr int kC  = 8;
constexpr int kF  = 256;
constexpr int kO  = 2048;   // OC*OF
constexpr int kCF = 2048;   // C*F
constexpr int kBN = 4096;   // B*N
constexpr int kMp = 4224;   // 4096 zn + 64 zx + 64 pad
}

// Scratch (device globals; no allocation allowed)
__device__ float g_w[kBN];
__device__ float g_t[kB * kCF];
__device__ __half g_adjh[(size_t)kB * kC * kF * kF];   // 67 MB: [b][c][a][d] fp16 hi
__device__ __half g_A2h[(size_t)kMp * kCF];            // 17.3 MB: zn|zx fp16
__device__ __half g_B2h[(size_t)kO * kCF];             // 8.4 MB: Wc fp16

// ---------------------------------------------------------------------------
// MUFU helpers
// ---------------------------------------------------------------------------
__device__ __forceinline__ float asqrt(float x) {
    float r; asm("sqrt.approx.f32 %0, %1;" : "=f"(r) : "f"(x)); return r;
}
__device__ __forceinline__ float arcp(float x) {
    float r; asm("rcp.approx.f32 %0, %1;" : "=f"(r) : "f"(x)); return r;
}
__device__ __forceinline__ float sgnroot(float a) {
    float s = asqrt(fmaxf(fabsf(a), 1e-8f));
    return (a == 0.0f) ? 0.0f : copysignf(s, a);
}

__device__ __forceinline__ float block_reduce_256(float v) {
    __shared__ float sh[8];
    int lane = threadIdx.x & 31, w = threadIdx.x >> 5;
    #pragma unroll
    for (int o = 16; o; o >>= 1) v += __shfl_xor_sync(0xffffffffu, v, o);
    if (lane == 0) sh[w] = v;
    __syncthreads();
    v = (threadIdx.x < 8) ? sh[threadIdx.x] : 0.0f;
    if (w == 0) {
        #pragma unroll
        for (int o = 4; o; o >>= 1) v += __shfl_xor_sync(0xffffffffu, v, o);
    }
    return v;   // valid on warp 0
}

__device__ __forceinline__ uint32_t s2u(const void* p) {
    uint32_t a;
    asm("{ .reg .u64 t; cvta.to.shared.u64 t, %1; cvt.u32.u64 %0, t; }" : "=r"(a) : "l"(p));
    return a;
}

// ---------------------------------------------------------------------------
// K2: w[b,n] = s1[b] * dot(nb[b,n], w2sum)   (w1sum/s1 folded in:
//     thread i only ever needs w1sum[i], w2sum[i] since 2048 = 8*256)
// ---------------------------------------------------------------------------
__global__ void k_w(const float* __restrict__ nb, const float* __restrict__ x,
                    const float* __restrict__ W1, const float* __restrict__ W2) {
    int bn = blockIdx.x;
    int b = bn >> 6;
    int i = threadIdx.x;
    float w1s = 0.f, w2s = 0.f;
    #pragma unroll
    for (int c = 0; c < kC; c++) {
        w1s += W1[c * kF + i];
        w2s += W2[c * kF + i];
    }
    float xsum = 0.f;
    #pragma unroll
    for (int k = 0; k < 8; k++) xsum += x[(size_t)b * kCF + k * kF + i];
    float s1 = block_reduce_256(w1s * xsum);        // valid on warp 0
    __syncthreads();                                 // protect sh[] reuse
    const float* p = nb + (size_t)bn * kCF;
    float acc = 0.f;
    #pragma unroll
    for (int k = 0; k < 8; k++) acc = fmaf(p[k * kF + i], w2s, acc);
    float s2 = block_reduce_256(acc);
    if (threadIdx.x == 0) g_w[bn] = s1 * s2;
}

// K3: t[b,c,f]
__global__ void k_t(const float* __restrict__ nb) {
    int bc = blockIdx.x;
    int b = bc >> 3, c = bc & 7;
    __shared__ float ws[kN];
    if (threadIdx.x < kN) ws[threadIdx.x] = g_w[b * kN + threadIdx.x];
    __syncthreads();
    int f = threadIdx.x;
    const float* p = nb + ((size_t)b * kN) * kCF + c * kF + f;
    float acc = 0.f;
    #pragma unroll 8
    for (int n = 0; n < kN; n++) acc = fmaf(ws[n], p[(size_t)n * kCF], acc);
    g_t[(size_t)bc * kF + f] = acc;
}

// ---------------------------------------------------------------------------
// K4: adj -> g_adjh fp16 (hi only) [b][c][a][d]  + fused zx (single sync/tile)
// ---------------------------------------------------------------------------
__global__ void __launch_bounds__(256) k_adj(const float* __restrict__ x) {
    int b = blockIdx.y;
    int at = blockIdx.x;
    __shared__ float xs[kCF];
    __shared__ float ts[kCF];
    __shared__ float zsh[16][8][8];   // [ai][warp][c]
    for (int i = threadIdx.x; i < kCF; i += 256) {
        xs[i] = x[(size_t)b * kCF + i];
        ts[i] = g_t[(size_t)b * kCF + i];
    }
    __syncthreads();
    int d = threadIdx.x;
    int lane = d & 31, w = d >> 5;
    float xd[kC], td[kC];
    #pragma unroll
    for (int c = 0; c < kC; c++) { xd[c] = xs[c * kF + d]; td[c] = ts[c * kF + d]; }

    for (int ai = 0; ai < 16; ai++) {
        int a = at * 16 + ai;
        float v[kC];
        float norm = 0.f;
        #pragma unroll
        for (int c = 0; c < kC; c++) {
            float va = xs[c * kF + a] * td[c] + xd[c] * ts[c * kF + a];
            float sv = sgnroot(va);
            v[c] = sv;
            norm += fabsf(sv);
        }
        float inv = arcp(norm + 1e-7f);
        float p[kC];
        #pragma unroll
        for (int c = 0; c < kC; c++) {
            float av = v[c] * inv;
            g_adjh[((size_t)(b * kC + c) * kF + a) * kF + d] = __float2half_rn(av);
            p[c] = av * xd[c];
        }
        #pragma unroll
        for (int o = 16; o; o >>= 1) {
            #pragma unroll
            for (int c = 0; c < kC; c++)
                p[c] += __shfl_xor_sync(0xffffffffu, p[c], o);
        }
        if (lane == 0) {
            #pragma unroll
            for (int c = 0; c < kC; c++) zsh[ai][w][c] = p[c];
        }
    }
    __syncthreads();
    if (threadIdx.x < 128) {
        int ai = threadIdx.x >> 3, c = threadIdx.x & 7;
        float z = 0.f;
        #pragma unroll
        for (int ww = 0; ww < 8; ww++) z += zsh[ai][ww][c];
        g_A2h[(size_t)(4096 + b) * kCF + c * kF + at * 16 + ai] = __float2half_rn(z);
    }
}

// ---------------------------------------------------------------------------
// K6: zn via HMMA: per (b,c)  C[64 n x 256 a] = NB[64 x 256 d] @ ADJ[256 a x 256 d]^T
// ---------------------------------------------------------------------------
namespace {
constexpr uint32_t kNbRegion = 32768;
constexpr uint32_t kAdjStage = 32768;
constexpr uint32_t kSmemZn   = kNbRegion + 2 * kAdjStage;  // 96 KB
}

__global__ void __launch_bounds__(256) k_zn_mma(const float* __restrict__ nb) {
    extern __shared__ char sm[];
    int tid = threadIdx.x, lane = tid & 31, wid = tid >> 5;
    int wm = wid >> 2, wn = wid & 3;             // 2(m) x 4(n); warp tile 32x64
    int bc = blockIdx.x;
    int b = bc >> 3, c = bc & 7;
    uint32_t sb = s2u(sm);
    uint32_t nbB = sb, adjB = sb + kNbRegion;

    const char* adj_bc = (const char*)(g_adjh + (size_t)bc * kF * kF);  // row 512 B
    const float* nb_bc = nb + ((size_t)b * kN) * kCF + c * kF;

    auto stage_load = [&](int q) {
        int srcoff = q * 128;
        uint32_t base = adjB + (uint32_t)(q & 1) * kAdjStage;
        #pragma unroll
        for (int k = 0; k < 8; k++) {
            int u = tid + (k << 8);          // 2048 quads: 256 rows x 8
            int row = u >> 3, q8 = u & 7;
            const char* g = adj_bc + (size_t)row * 512 + srcoff + q8 * 16;
            uint32_t so = base + (uint32_t)(row * 128) + (uint32_t)((q8 * 16) ^ ((row & 7) << 4));
            asm volatile("cp.async.cg.shared.global [%0], [%1], 16;" :: "r"(so), "l"(g));
        }
        asm volatile("cp.async.commit_group;");
    };

    stage_load(0);

    // NB load + fp16 convert into smem chunks (overlaps first adj load)
    #pragma unroll
    for (int itc = 0; itc < 8; itc++) {
        int e = tid + (itc << 8);            // 2048 groups: 64 rows x 32 (8 d each)
        int row = e >> 5, d0 = (e & 31) << 3;
        float4 v0 = *(const float4*)(nb_bc + (size_t)row * kCF + d0);
        float4 v1 = *(const float4*)(nb_bc + (size_t)row * kCF + d0 + 4);
        float v[8] = {v0.x, v0.y, v0.z, v0.w, v1.x, v1.y, v1.z, v1.w};
        uint32_t hw[4];
        #pragma unroll
        for (int j = 0; j < 4; j++) {
            __half h0 = __float2half_rn(v[2 * j]), h1 = __float2half_rn(v[2 * j + 1]);
            hw[j] = (uint32_t)__half_as_ushort(h0) | ((uint32_t)__half_as_ushort(h1) << 16);
        }
        int chunk = d0 >> 6, cw = d0 & 63;
        uint32_t off = (uint32_t)(chunk * 8192 + row * 128) + (uint32_t)((cw * 2) ^ ((row & 7) << 4));
        *(uint4*)(sm + off) = make_uint4(hw[0], hw[1], hw[2], hw[3]);
    }

    float acc[2][8][4];
    #pragma unroll
    for (int i = 0; i < 2; i++)
        #pragma unroll
        for (int j = 0; j < 8; j++)
            #pragma unroll
            for (int r = 0; r < 4; r++) acc[i][j][r] = 0.f;

    int aRow0 = wm * 32 + (lane & 15);
    int aKofs = (lane >> 4) << 4;
    int bRow0 = wn * 64 + (lane & 7) + ((lane & 16) >> 1);
    int bKofs = (lane & 8) << 1;

    const int NIT = 4;
    for (int it = 0; it < NIT; it++) {
        if (it + 1 < NIT) {
            stage_load(it + 1);
            asm volatile("cp.async.wait_group 1;");
        } else {
            asm volatile("cp.async.wait_group 0;");
        }
        __syncthreads();
        uint32_t aH = nbB + (uint32_t)it * 8192u;
        uint32_t bBase = adjB + (uint32_t)(it & 1) * kAdjStage;
        #pragma unroll
        for (int k16 = 0; k16 < 4; k16++) {
            int kb = k16 * 32;
            uint32_t af[2][4];
            #pragma unroll
            for (int mt = 0; mt < 2; mt++) {
                int row = aRow0 + mt * 16;
                uint32_t sw = ((kb + aKofs) ^ ((row & 7) << 4)) + row * 128;
                asm volatile("ldmatrix.sync.aligned.m8n8.x4.shared.b16 {%0,%1,%2,%3}, [%4];"
                             : "=r"(af[mt][0]), "=r"(af[mt][1]), "=r"(af[mt][2]), "=r"(af[mt][3])
                             : "r"(aH + sw));
            }
            uint32_t bf[4][4];
            #pragma unroll
            for (int nt = 0; nt < 4; nt++) {
                int row = bRow0 + nt * 16;
                uint32_t bd = bBase + row * 128 + ((kb + bKofs) ^ ((row & 7) << 4));
                asm volatile("ldmatrix.sync.aligned.m8n8.x4.shared.b16 {%0,%1,%2,%3}, [%4];"
                             : "=r"(bf[nt][0]), "=r"(bf[nt][1]), "=r"(bf[nt][2]), "=r"(bf[nt][3])
                             : "r"(bd));
            }
            #pragma unroll
            for (int mt = 0; mt < 2; mt++)
                #pragma unroll
                for (int n8 = 0; n8 < 8; n8++) {
                    uint32_t b0 = bf[n8 >> 1][(n8 & 1) * 2 + 0];
                    uint32_t b1 = bf[n8 >> 1][(n8 & 1) * 2 + 1];
                    asm volatile(
                        "mma.sync.aligned.m16n8k16.row.col.f32.f16.f16.f32 "
                        "{%0,%1,%2,%3}, {%4,%5,%6,%7}, {%8,%9}, {%0,%1,%2,%3};"
                        : "+f"(acc[mt][n8][0]), "+f"(acc[mt][n8][1]),
                          "+f"(acc[mt][n8][2]), "+f"(acc[mt][n8][3])
                        : "r"(af[mt][0]), "r"(af[mt][1]), "r"(af[mt][2]), "r"(af[mt][3]),
                          "r"(b0), "r"(b1));
                }
        }
        __syncthreads();
    }

    int g = lane >> 2, tig = lane & 3;
    #pragma unroll
    for (int mt = 0; mt < 2; mt++) {
        #pragma unroll
        for (int half = 0; half < 2; half++) {
            int lr = wm * 32 + mt * 16 + g + half * 8;
            __half* dst = g_A2h + (size_t)(b * kN + lr) * kCF + c * kF;
            #pragma unroll
            for (int n8 = 0; n8 < 8; n8++) {
                int col = wn * 64 + n8 * 8 + tig * 2;
                *(__half2*)(dst + col) =
                    __halves2half2(__float2half_rn(acc[mt][n8][half * 2]),
                                   __float2half_rn(acc[mt][n8][half * 2 + 1]));
            }
        }
    }
}

// ---------------------------------------------------------------------------
// K7: Wc -> g_B2h fp16 (vectorized)
// ---------------------------------------------------------------------------
__global__ void k_wconv(const float* __restrict__ Wc) {
    int o = blockIdx.x;
    __half* rowb = g_B2h + (size_t)o * kCF;
    const float* src = Wc + (size_t)o * kCF;
    #pragma unroll
    for (int it = 0; it < 2; it++) {
        int j = (threadIdx.x + it * 256) * 4;
        float4 v = *(const float4*)(src + j);
        __half2 h0 = __halves2half2(__float2half_rn(v.x), __float2half_rn(v.y));
        __half2 h1 = __halves2half2(__float2half_rn(v.z), __float2half_rn(v.w));
        *(__half2*)(rowb + j)     = h0;
        *(__half2*)(rowb + j + 2) = h1;
    }
}

// ---------------------------------------------------------------------------
// K8: single-term fp16 NT GEMM: C[4224,2048] = A2h @ B2h^T, K=2048
// CTA 128(M) x 256(N), 512 threads (16 warps 4x4, warp tile 32x64),
// double-buffered cp.async, NIT=32.  L2 traffic 396 MB (was 528).
// ---------------------------------------------------------------------------
namespace {
constexpr uint32_t kStageG = 49152;   // A 16K + B 32K
constexpr uint32_t kSmemG  = 2 * kStageG;
}

__global__ void __launch_bounds__(512) k_mma2(float* __restrict__ x_out,
                                              float* __restrict__ n_out) {
    extern __shared__ char sm[];
    int tid = threadIdx.x, lane = tid & 31, wid = tid >> 5;
    int wm = wid >> 2, wn = wid & 3;             // 4(m) x 4(n); warp tile 32x64
    int bm = blockIdx.y * 128, bn = blockIdx.x * 256;
    uint32_t sbase = s2u(sm);

    const char* Ag = (const char*)(g_A2h + (size_t)bm * kCF);   // row 4096 B
    const char* Bg = (const char*)(g_B2h + (size_t)bn * kCF);   // row 4096 B

    auto stage_load = [&](int it) {
        int koff = it * 128;                     // 64 halves
        uint32_t base = sbase + (uint32_t)(it & 1) * kStageG;
        #pragma unroll
        for (int k = 0; k < 6; k++) {
            int u = tid + (k << 9);              // 0..3071 quads
            int isB = (u >= 1024);
            int v = isB ? (u - 1024) : u;        // A: 1024 quads, B: 2048 quads
            int row = v >> 3, q8 = v & 7;
            const char* g = (isB ? Bg : Ag) + (size_t)row * 4096 + koff + q8 * 16;
            uint32_t so = base + (uint32_t)isB * 16384u + (uint32_t)(row * 128)
                          + (uint32_t)((q8 * 16) ^ ((row & 7) << 4));
            asm volatile("cp.async.cg.shared.global [%0], [%1], 16;" :: "r"(so), "l"(g));
        }
        asm volatile("cp.async.commit_group;");
    };

    float acc[2][8][4];
    #pragma unroll
    for (int i = 0; i < 2; i++)
        #pragma unroll
        for (int j = 0; j < 8; j++)
            #pragma unroll
            for (int r = 0; r < 4; r++) acc[i][j][r] = 0.f;

    int aRow0 = wm * 32 + (lane & 15);
    int aKofs = (lane >> 4) << 4;
    int bRow0 = wn * 64 + (lane & 7) + ((lane & 16) >> 1);
    int bKofs = (lane & 8) << 1;

    stage_load(0);
    const int NIT = 32;
    for (int it = 0; it < NIT; it++) {
        int s = it & 1;
        if (it + 1 < NIT) {
            stage_load(it + 1);
            asm volatile("cp.async.wait_group 1;");
        } else {
            asm volatile("cp.async.wait_group 0;");
        }
        __syncthreads();
        uint32_t aA = sbase + (uint32_t)s * kStageG;
        uint32_t aB = aA + 16384u;
        #pragma unroll
        for (int k16 = 0; k16 < 4; k16++) {
            int kb = k16 * 32;
            uint32_t af[2][4];
            #pragma unroll
            for (int mt = 0; mt < 2; mt++) {
                int row = aRow0 + mt * 16;
                uint32_t ad = aA + row * 128 + ((kb + aKofs) ^ ((row & 7) << 4));
                asm volatile("ldmatrix.sync.aligned.m8n8.x4.shared.b16 {%0,%1,%2,%3}, [%4];"
                             : "=r"(af[mt][0]), "=r"(af[mt][1]), "=r"(af[mt][2]), "=r"(af[mt][3])
                             : "r"(ad));
            }
            uint32_t bf[4][4];
            #pragma unroll
            for (int nt = 0; nt < 4; nt++) {
                int row = bRow0 + nt * 16;
                uint32_t bd = aB + row * 128 + ((kb + bKofs) ^ ((row & 7) << 4));
                asm volatile("ldmatrix.sync.aligned.m8n8.x4.shared.b16 {%0,%1,%2,%3}, [%4];"
                             : "=r"(bf[nt][0]), "=r"(bf[nt][1]), "=r"(bf[nt][2]), "=r"(bf[nt][3])
                             : "r"(bd));
            }
            #pragma unroll
            for (int mt = 0; mt < 2; mt++)
                #pragma unroll
                for (int n8 = 0; n8 < 8; n8++) {
                    uint32_t b0 = bf[n8 >> 1][(n8 & 1) * 2 + 0];
                    uint32_t b1 = bf[n8 >> 1][(n8 & 1) * 2 + 1];
                    asm volatile(
                        "mma.sync.aligned.m16n8k16.row.col.f32.f16.f16.f32 "
                        "{%0,%1,%2,%3}, {%4,%5,%6,%7}, {%8,%9}, {%0,%1,%2,%3};"
                        : "+f"(acc[mt][n8][0]), "+f"(acc[mt][n8][1]),
                          "+f"(acc[mt][n8][2]), "+f"(acc[mt][n8][3])
                        : "r"(af[mt][0]), "r"(af[mt][1]), "r"(af[mt][2]), "r"(af[mt][3]),
                          "r"(b0), "r"(b1));
                }
        }
        __syncthreads();
    }

    int g = lane >> 2, tig = lane & 3;
    #pragma unroll
    for (int mt = 0; mt < 2; mt++) {
        #pragma unroll
        for (int half = 0; half < 2; half++) {
            int gm = bm + wm * 32 + mt * 16 + g + half * 8;
            if (gm < 4160) {
                float* dst = (gm < 4096)
                    ? n_out + (size_t)gm * kO
                    : x_out + (size_t)(gm - 4096) * kO;
                #pragma unroll
                for (int n8 = 0; n8 < 8; n8++) {
                    int col = bn + wn * 64 + n8 * 8 + tig * 2;
                    float2 v = half ? make_float2(acc[mt][n8][2], acc[mt][n8][3])
                                    : make_float2(acc[mt][n8][0], acc[mt][n8][1]);
                    *(float2*)(dst + col) = v;
                }
            }
        }
    }
}

// ---------------------------------------------------------------------------
extern "C" void kernel_launch(void* const* d_in, const int* in_sizes, int n_in,
                              void* d_out, int out_size) {
    const float* x  = (const float*)d_in[0];
    const float* nb = (const float*)d_in[1];
    const float* W1 = (const float*)d_in[2];
    const float* W2 = (const float*)d_in[3];
    const float* Wc = (const float*)d_in[4];
    float* out = (float*)d_out;
    float* x_out = out;                          // (B, OC, OF)
    float* n_out = out + (size_t)kB * kO;        // (B, N, OC, OF)

    cudaFuncSetAttribute(k_zn_mma, cudaFuncAttributeMaxDynamicSharedMemorySize, kSmemZn);
    cudaFuncSetAttribute(k_mma2, cudaFuncAttributeMaxDynamicSharedMemorySize, kSmemG);

    k_w<<<kBN, 256>>>(nb, x, W1, W2);
    k_t<<<kB * kC, 256>>>(nb);
    k_adj<<<dim3(16, kB), 256>>>(x);
    k_zn_mma<<<kB * kC, 256, kSmemZn>>>(nb);
    k_wconv<<<kO, 256>>>(Wc);
    k_mma2<<<dim3(8, 33), 512, kSmemG>>>(x_out, n_out);
}